// round 15
// baseline (speedup 1.0000x reference)
#include <cuda_runtime.h>
#include <cuda_fp16.h>
#include <cstdint>

// COO SpMM: out[src[e], :] += att[e] * X[dst[e], :], D = 128 fp32.
//
// R14 champion (135.9us) with ONE spmm change: the 4 scalar FFMAs per edge
// become 2 packed fma.rn.f32x2 (Blackwell 64-bit paired FFMA, PTX-only —
// ptxas never auto-fuses). Everything else byte-identical.
//
//   1. prep_hist: X fp32->fp16 convert + src histogram (zero-invariant
//      counters: spmm resets them; statics start zero)
//   2-4. scan1 / scan2 / scan3 -> rowptr + cursor
//   5. scatter packed (dst<<8 byte offset, att_f32), sorted by src
//   6. spmm: warp-per-node gather + f32x2 FMA, streaming store
//
// PACKED CSR only (R3+R8: padded layouts ~4x slower).
// Footprint: X_half 25.6MB + meta 25.6MB + ptrs ~1.2MB = ~53MB << 126MB L2.

#define SCAN_BLK 1024
#define N_MAX 131072
#define E_MAX 3276800

__device__ int    g_count[N_MAX];     // histogram; zero before & after each call
__device__ int    g_cursor[N_MAX];    // scatter fill cursor
__device__ int    g_rowptr[N_MAX + 1];
__device__ int    g_blocksums[N_MAX / SCAN_BLK];
__device__ int2   g_edge[E_MAX];                    // (dst*256, att bits)
__device__ uint2  g_xh[(size_t)N_MAX * 32];         // X fp16: 256B per row

__device__ __forceinline__ bool detect64(const void* edges) {
    const int* w = (const int*)edges;
    return (w[1] == 0 && w[3] == 0 && w[5] == 0);   // ids << 2^31
}

__device__ __forceinline__ unsigned h2_bits(__half2 h) {
    return *reinterpret_cast<unsigned*>(&h);
}

// Fused: convert X -> fp16 (DRAM-stream bound) + histogram src (atomic bound).
__global__ void prep_hist_kernel(const float4* __restrict__ X, int N,
                                 const void* __restrict__ edges, int E) {
    int stride = gridDim.x * blockDim.x;
    int tid = blockIdx.x * blockDim.x + threadIdx.x;

    int n4 = N * 32;
    for (int i = tid; i < n4; i += stride) {
        float4 v = __ldcs(X + i);
        g_xh[i] = make_uint2(h2_bits(__floats2half2_rn(v.x, v.y)),
                             h2_bits(__floats2half2_rn(v.z, v.w)));
    }

    const bool is64 = detect64(edges);
    if (is64) {
        const long long* s = (const long long*)edges;
        for (int e = tid; e < E; e += stride)
            atomicAdd(&g_count[(int)s[e]], 1);
    } else {
        const int* s = (const int*)edges;
        for (int e = tid; e < E; e += stride)
            atomicAdd(&g_count[s[e]], 1);
    }
}

__global__ void scan1_kernel() {
    __shared__ int sh[SCAN_BLK];
    int i = blockIdx.x * SCAN_BLK + threadIdx.x;
    int v = g_count[i];
    sh[threadIdx.x] = v;
    __syncthreads();
    #pragma unroll
    for (int off = 1; off < SCAN_BLK; off <<= 1) {
        int t = (threadIdx.x >= off) ? sh[threadIdx.x - off] : 0;
        __syncthreads();
        sh[threadIdx.x] += t;
        __syncthreads();
    }
    g_rowptr[i] = sh[threadIdx.x] - v;
    if (threadIdx.x == SCAN_BLK - 1) g_blocksums[blockIdx.x] = sh[threadIdx.x];
}

__global__ void scan2_kernel(int nblocks) {
    __shared__ int sh[128];
    int v = (threadIdx.x < nblocks) ? g_blocksums[threadIdx.x] : 0;
    sh[threadIdx.x] = v;
    __syncthreads();
    #pragma unroll
    for (int off = 1; off < 128; off <<= 1) {
        int t = (threadIdx.x >= off) ? sh[threadIdx.x - off] : 0;
        __syncthreads();
        sh[threadIdx.x] += t;
        __syncthreads();
    }
    if (threadIdx.x < nblocks) g_blocksums[threadIdx.x] = sh[threadIdx.x] - v;
}

__global__ void scan3_kernel(int npad) {
    int i = blockIdx.x * blockDim.x + threadIdx.x;
    if (i < npad) {
        int r = g_rowptr[i] + g_blocksums[i / SCAN_BLK];
        g_rowptr[i] = r;
        g_cursor[i] = r;
    }
}

// Scatter packed (dst<<8, att bits): byte-offset shift runs here (ALU idle).
__global__ void scatter_kernel(const void* __restrict__ edges,
                               const float* __restrict__ att, int E) {
    const bool is64 = detect64(edges);
    int half = E >> 1;
    int stride = gridDim.x * blockDim.x;
    for (int i = blockIdx.x * blockDim.x + threadIdx.x; i < half; i += stride) {
        int s0, s1, d0, d1;
        if (is64) {
            longlong2 s = __ldcs((const longlong2*)edges + i);
            longlong2 d = __ldcs((const longlong2*)((const long long*)edges + E) + i);
            s0 = (int)s.x; s1 = (int)s.y; d0 = (int)d.x; d1 = (int)d.y;
        } else {
            int2 s = __ldcs((const int2*)edges + i);
            int2 d = __ldcs((const int2*)((const int*)edges + E) + i);
            s0 = s.x; s1 = s.y; d0 = d.x; d1 = d.y;
        }
        float2 a = __ldcs((const float2*)att + i);
        int p0 = atomicAdd(&g_cursor[s0], 1);
        g_edge[p0] = make_int2(d0 << 8, __float_as_int(a.x));
        int p1 = atomicAdd(&g_cursor[s1], 1);
        g_edge[p1] = make_int2(d1 << 8, __float_as_int(a.y));
    }
    if (blockIdx.x == 0 && threadIdx.x == 0 && (E & 1)) {
        int e = E - 1;
        int s, d;
        if (is64) {
            s = (int)((const long long*)edges)[e];
            d = (int)((const long long*)edges)[(long long)E + e];
        } else {
            s = ((const int*)edges)[e];
            d = ((const int*)edges)[(long long)E + e];
        }
        int p = atomicAdd(&g_cursor[s], 1);
        g_edge[p] = make_int2(d << 8, __float_as_int(att[e]));
    }
}

// Per-edge FMA with packed f32x2: 2 FFMA2 instead of 4 FFMA.
__device__ __forceinline__ void edge_fma2(int2 m, uint2 h,
                                          unsigned long long& accA,
                                          unsigned long long& accB) {
    float2 lo = __half22float2(*(__half2*)&h.x);
    float2 hi = __half22float2(*(__half2*)&h.y);
    float a = __int_as_float(m.y);
    unsigned long long vA, vB, aa;
    asm("mov.b64 %0, {%1, %2};" : "=l"(vA) : "f"(lo.x), "f"(lo.y));
    asm("mov.b64 %0, {%1, %2};" : "=l"(vB) : "f"(hi.x), "f"(hi.y));
    asm("mov.b64 %0, {%1, %1};" : "=l"(aa) : "f"(a));
    asm("fma.rn.f32x2 %0, %1, %2, %0;" : "+l"(accA) : "l"(vA), "l"(aa));
    asm("fma.rn.f32x2 %0, %1, %2, %0;" : "+l"(accB) : "l"(vB), "l"(aa));
}

// Warp per node: lane l owns feature quad l. Gather address = lane base +
// byte offset (1 IADD). fp16 gather (8B/lane = 256B/row coalesced), packed
// f32x2 accumulate, 8 gathers in flight, streaming store. Resets g_count.
__global__ void __launch_bounds__(256) spmm_kernel(float4* __restrict__ out, int N) {
    int lane = threadIdx.x & 31;
    int node = (blockIdx.x * blockDim.x + threadIdx.x) >> 5;
    if (node >= N) return;

    int e = __ldg(&g_rowptr[node]);
    int end = __ldg(&g_rowptr[node + 1]);
    if (lane == 0) g_count[node] = 0;       // restore zero-invariant

    const char* xb = (const char*)g_xh + (lane << 3);   // lane's 8B within row
    unsigned long long accA = 0ULL, accB = 0ULL;        // (f32,f32) pairs

    for (; e + 8 <= end; e += 8) {
        int2 m[8]; uint2 h[8];
        #pragma unroll
        for (int k = 0; k < 8; k++) m[k] = __ldg(&g_edge[e + k]);
        #pragma unroll
        for (int k = 0; k < 8; k++)
            h[k] = __ldg((const uint2*)(xb + (unsigned)m[k].x));
        #pragma unroll
        for (int k = 0; k < 8; k++) edge_fma2(m[k], h[k], accA, accB);
    }
    for (; e + 2 <= end; e += 2) {
        int2 m0 = __ldg(&g_edge[e]);
        int2 m1 = __ldg(&g_edge[e + 1]);
        uint2 h0 = __ldg((const uint2*)(xb + (unsigned)m0.x));
        uint2 h1 = __ldg((const uint2*)(xb + (unsigned)m1.x));
        edge_fma2(m0, h0, accA, accB);
        edge_fma2(m1, h1, accA, accB);
    }
    if (e < end) {
        int2 m = __ldg(&g_edge[e]);
        uint2 h = __ldg((const uint2*)(xb + (unsigned)m.x));
        edge_fma2(m, h, accA, accB);
    }

    float4 acc;
    asm("mov.b64 {%0, %1}, %2;" : "=f"(acc.x), "=f"(acc.y) : "l"(accA));
    asm("mov.b64 {%0, %1}, %2;" : "=f"(acc.z), "=f"(acc.w) : "l"(accB));
    __stcs(out + (size_t)node * 32 + lane, acc);
}

extern "C" void kernel_launch(void* const* d_in, const int* in_sizes, int n_in,
                              void* d_out, int out_size) {
    const void* edges = d_in[0];               // (2, E) int32 or int64
    const float* att = (const float*)d_in[1];  // (E,)
    const float4* X = (const float4*)d_in[3];  // (N, 128) fp32
    float4* out = (float4*)d_out;

    int E = in_sizes[1];
    int N = out_size / 128;
    int npad = ((N + 1 + SCAN_BLK - 1) / SCAN_BLK) * SCAN_BLK;
    int nsb = npad / SCAN_BLK;

    prep_hist_kernel<<<2048, 256>>>(X, N, edges, E);
    scan1_kernel<<<nsb, SCAN_BLK>>>();
    scan2_kernel<<<1, 128>>>(nsb);
    scan3_kernel<<<(npad + 255) / 256, 256>>>(npad);
    scatter_kernel<<<2048, 256>>>(edges, att, E);
    spmm_kernel<<<(N + 7) / 8, 256>>>(out, N);
}

// round 16
// speedup vs baseline: 1.0128x; 1.0128x over previous
#include <cuda_runtime.h>
#include <cuda_fp16.h>
#include <cstdint>

// COO SpMM: out[src[e], :] += att[e] * X[dst[e], :], D = 128 fp32.
//
// R14 champion (135.9us) with ONE spmm change: software-pipelined meta
// prefetch (double-buffered). Iteration i+1's 8 edge metas are loaded before
// iteration i's gathers are consumed, hiding the ~260cyc meta->gather L2
// dependence that holds spmm at ~53% effective issue.
//
//   1. prep_hist: X fp32->fp16 convert + src histogram (zero-invariant
//      counters: spmm resets them; statics start zero)
//   2-4. scan1 / scan2 / scan3 -> rowptr + cursor
//   5. scatter packed (dst<<8 byte offset, att_f32), sorted by src
//   6. spmm: warp-per-node, pipelined meta, fp16 gather, fp32 FMA
//
// PACKED CSR only (R3+R8: padded layouts ~4x slower).
// Footprint: X_half 25.6MB + meta 25.6MB + ptrs ~1.2MB = ~53MB << 126MB L2.

#define SCAN_BLK 1024
#define N_MAX 131072
#define E_MAX 3276800

__device__ int    g_count[N_MAX];     // histogram; zero before & after each call
__device__ int    g_cursor[N_MAX];    // scatter fill cursor
__device__ int    g_rowptr[N_MAX + 1];
__device__ int    g_blocksums[N_MAX / SCAN_BLK];
__device__ int2   g_edge[E_MAX];                    // (dst*256, att bits)
__device__ uint2  g_xh[(size_t)N_MAX * 32];         // X fp16: 256B per row

__device__ __forceinline__ bool detect64(const void* edges) {
    const int* w = (const int*)edges;
    return (w[1] == 0 && w[3] == 0 && w[5] == 0);   // ids << 2^31
}

__device__ __forceinline__ unsigned h2_bits(__half2 h) {
    return *reinterpret_cast<unsigned*>(&h);
}

// Fused: convert X -> fp16 (DRAM-stream bound) + histogram src (atomic bound).
__global__ void prep_hist_kernel(const float4* __restrict__ X, int N,
                                 const void* __restrict__ edges, int E) {
    int stride = gridDim.x * blockDim.x;
    int tid = blockIdx.x * blockDim.x + threadIdx.x;

    int n4 = N * 32;
    for (int i = tid; i < n4; i += stride) {
        float4 v = __ldcs(X + i);
        g_xh[i] = make_uint2(h2_bits(__floats2half2_rn(v.x, v.y)),
                             h2_bits(__floats2half2_rn(v.z, v.w)));
    }

    const bool is64 = detect64(edges);
    if (is64) {
        const long long* s = (const long long*)edges;
        for (int e = tid; e < E; e += stride)
            atomicAdd(&g_count[(int)s[e]], 1);
    } else {
        const int* s = (const int*)edges;
        for (int e = tid; e < E; e += stride)
            atomicAdd(&g_count[s[e]], 1);
    }
}

__global__ void scan1_kernel() {
    __shared__ int sh[SCAN_BLK];
    int i = blockIdx.x * SCAN_BLK + threadIdx.x;
    int v = g_count[i];
    sh[threadIdx.x] = v;
    __syncthreads();
    #pragma unroll
    for (int off = 1; off < SCAN_BLK; off <<= 1) {
        int t = (threadIdx.x >= off) ? sh[threadIdx.x - off] : 0;
        __syncthreads();
        sh[threadIdx.x] += t;
        __syncthreads();
    }
    g_rowptr[i] = sh[threadIdx.x] - v;
    if (threadIdx.x == SCAN_BLK - 1) g_blocksums[blockIdx.x] = sh[threadIdx.x];
}

__global__ void scan2_kernel(int nblocks) {
    __shared__ int sh[128];
    int v = (threadIdx.x < nblocks) ? g_blocksums[threadIdx.x] : 0;
    sh[threadIdx.x] = v;
    __syncthreads();
    #pragma unroll
    for (int off = 1; off < 128; off <<= 1) {
        int t = (threadIdx.x >= off) ? sh[threadIdx.x - off] : 0;
        __syncthreads();
        sh[threadIdx.x] += t;
        __syncthreads();
    }
    if (threadIdx.x < nblocks) g_blocksums[threadIdx.x] = sh[threadIdx.x] - v;
}

__global__ void scan3_kernel(int npad) {
    int i = blockIdx.x * blockDim.x + threadIdx.x;
    if (i < npad) {
        int r = g_rowptr[i] + g_blocksums[i / SCAN_BLK];
        g_rowptr[i] = r;
        g_cursor[i] = r;
    }
}

// Scatter packed (dst<<8, att bits): byte-offset shift runs here (ALU idle).
__global__ void scatter_kernel(const void* __restrict__ edges,
                               const float* __restrict__ att, int E) {
    const bool is64 = detect64(edges);
    int half = E >> 1;
    int stride = gridDim.x * blockDim.x;
    for (int i = blockIdx.x * blockDim.x + threadIdx.x; i < half; i += stride) {
        int s0, s1, d0, d1;
        if (is64) {
            longlong2 s = __ldcs((const longlong2*)edges + i);
            longlong2 d = __ldcs((const longlong2*)((const long long*)edges + E) + i);
            s0 = (int)s.x; s1 = (int)s.y; d0 = (int)d.x; d1 = (int)d.y;
        } else {
            int2 s = __ldcs((const int2*)edges + i);
            int2 d = __ldcs((const int2*)((const int*)edges + E) + i);
            s0 = s.x; s1 = s.y; d0 = d.x; d1 = d.y;
        }
        float2 a = __ldcs((const float2*)att + i);
        int p0 = atomicAdd(&g_cursor[s0], 1);
        g_edge[p0] = make_int2(d0 << 8, __float_as_int(a.x));
        int p1 = atomicAdd(&g_cursor[s1], 1);
        g_edge[p1] = make_int2(d1 << 8, __float_as_int(a.y));
    }
    if (blockIdx.x == 0 && threadIdx.x == 0 && (E & 1)) {
        int e = E - 1;
        int s, d;
        if (is64) {
            s = (int)((const long long*)edges)[e];
            d = (int)((const long long*)edges)[(long long)E + e];
        } else {
            s = ((const int*)edges)[e];
            d = ((const int*)edges)[(long long)E + e];
        }
        int p = atomicAdd(&g_cursor[s], 1);
        g_edge[p] = make_int2(d << 8, __float_as_int(att[e]));
    }
}

__device__ __forceinline__ void edge_fma_m(int2 m, uint2 h, float4& acc) {
    float a = __int_as_float(m.y);
    float2 lo = __half22float2(*(__half2*)&h.x);
    float2 hi = __half22float2(*(__half2*)&h.y);
    acc.x = fmaf(a, lo.x, acc.x); acc.y = fmaf(a, lo.y, acc.y);
    acc.z = fmaf(a, hi.x, acc.z); acc.w = fmaf(a, hi.y, acc.w);
}

// Warp per node: lane l owns feature quad l. Gather address = lane base +
// byte offset (1 IADD). Meta double-buffered: next iteration's 8 metas load
// while current iteration's gathers+FMAs retire. Streaming store. Resets
// g_count (zero-invariant).
__global__ void __launch_bounds__(256) spmm_kernel(float4* __restrict__ out, int N) {
    int lane = threadIdx.x & 31;
    int node = (blockIdx.x * blockDim.x + threadIdx.x) >> 5;
    if (node >= N) return;

    int e = __ldg(&g_rowptr[node]);
    int end = __ldg(&g_rowptr[node + 1]);
    if (lane == 0) g_count[node] = 0;       // restore zero-invariant

    const char* xb = (const char*)g_xh + (lane << 3);   // lane's 8B within row
    float4 acc = make_float4(0.f, 0.f, 0.f, 0.f);

    int nfull = (end - e) >> 3;             // full 8-edge blocks
    if (nfull > 0) {
        int2 m[8];
        #pragma unroll
        for (int k = 0; k < 8; k++) m[k] = __ldg(&g_edge[e + k]);

        for (int b = 1; b < nfull; b++) {
            int2 mn[8];
            int en = e + b * 8;
            #pragma unroll
            for (int k = 0; k < 8; k++) mn[k] = __ldg(&g_edge[en + k]);  // prefetch

            uint2 h[8];
            #pragma unroll
            for (int k = 0; k < 8; k++)
                h[k] = __ldg((const uint2*)(xb + (unsigned)m[k].x));
            #pragma unroll
            for (int k = 0; k < 8; k++) edge_fma_m(m[k], h[k], acc);
            #pragma unroll
            for (int k = 0; k < 8; k++) m[k] = mn[k];
        }
        {   // drain last block
            uint2 h[8];
            #pragma unroll
            for (int k = 0; k < 8; k++)
                h[k] = __ldg((const uint2*)(xb + (unsigned)m[k].x));
            #pragma unroll
            for (int k = 0; k < 8; k++) edge_fma_m(m[k], h[k], acc);
        }
        e += nfull * 8;
    }
    for (; e + 2 <= end; e += 2) {
        int2 m0 = __ldg(&g_edge[e]);
        int2 m1 = __ldg(&g_edge[e + 1]);
        uint2 h0 = __ldg((const uint2*)(xb + (unsigned)m0.x));
        uint2 h1 = __ldg((const uint2*)(xb + (unsigned)m1.x));
        edge_fma_m(m0, h0, acc);
        edge_fma_m(m1, h1, acc);
    }
    if (e < end) {
        int2 m = __ldg(&g_edge[e]);
        uint2 h = __ldg((const uint2*)(xb + (unsigned)m.x));
        edge_fma_m(m, h, acc);
    }

    __stcs(out + (size_t)node * 32 + lane, acc);
}

extern "C" void kernel_launch(void* const* d_in, const int* in_sizes, int n_in,
                              void* d_out, int out_size) {
    const void* edges = d_in[0];               // (2, E) int32 or int64
    const float* att = (const float*)d_in[1];  // (E,)
    const float4* X = (const float4*)d_in[3];  // (N, 128) fp32
    float4* out = (float4*)d_out;

    int E = in_sizes[1];
    int N = out_size / 128;
    int npad = ((N + 1 + SCAN_BLK - 1) / SCAN_BLK) * SCAN_BLK;
    int nsb = npad / SCAN_BLK;

    prep_hist_kernel<<<2048, 256>>>(X, N, edges, E);
    scan1_kernel<<<nsb, SCAN_BLK>>>();
    scan2_kernel<<<1, 128>>>(nsb);
    scan3_kernel<<<(npad + 255) / 256, 256>>>(npad);
    scatter_kernel<<<2048, 256>>>(edges, att, E);
    spmm_kernel<<<(N + 7) / 8, 256>>>(out, N);
}

// round 17
// speedup vs baseline: 1.0684x; 1.0550x over previous
#include <cuda_runtime.h>
#include <cuda_fp16.h>
#include <cstdint>

// COO SpMM: out[src[e], :] += att[e] * X[dst[e], :], D = 128 fp32.
//
// R14 champion (135.9us) with ONE spmm change: edge-pair split across warp
// halves. Lanes 0-15 process even edges, lanes 16-31 odd edges of the SAME
// node's list (no cross-node divergence). Each lane gathers uint4 (16B x 16
// lanes = 256B row), halving meta/addr/gather instruction count per edge on
// the issue-bound kernel. Branch-free odd tail (upper half att=0); epilogue
// combines halves with 8 shfl_xor + 8 FADD, coalesced STG.128.
//
//   1. prep_hist: X fp32->fp16 convert + src histogram (zero-invariant
//      counters: spmm resets them; statics start zero)
//   2-4. scan1 / scan2 / scan3 -> rowptr + cursor
//   5. scatter packed (dst<<8 byte offset, att_f32), sorted by src
//   6. spmm: warp-per-node, half-warp edge pairing, fp16 gather, fp32 FMA
//
// PACKED CSR only (R3+R8: padded layouts ~4x slower).
// Footprint: X_half 25.6MB + meta 25.6MB + ptrs ~1.2MB = ~53MB << 126MB L2.

#define SCAN_BLK 1024
#define N_MAX 131072
#define E_MAX 3276800

__device__ int    g_count[N_MAX];     // histogram; zero before & after each call
__device__ int    g_cursor[N_MAX];    // scatter fill cursor
__device__ int    g_rowptr[N_MAX + 1];
__device__ int    g_blocksums[N_MAX / SCAN_BLK];
__device__ int2   g_edge[E_MAX];                    // (dst*256, att bits)
__device__ uint2  g_xh[(size_t)N_MAX * 32];         // X fp16: 256B per row

__device__ __forceinline__ bool detect64(const void* edges) {
    const int* w = (const int*)edges;
    return (w[1] == 0 && w[3] == 0 && w[5] == 0);   // ids << 2^31
}

__device__ __forceinline__ unsigned h2_bits(__half2 h) {
    return *reinterpret_cast<unsigned*>(&h);
}

// Fused: convert X -> fp16 (DRAM-stream bound) + histogram src (atomic bound).
__global__ void prep_hist_kernel(const float4* __restrict__ X, int N,
                                 const void* __restrict__ edges, int E) {
    int stride = gridDim.x * blockDim.x;
    int tid = blockIdx.x * blockDim.x + threadIdx.x;

    int n4 = N * 32;
    for (int i = tid; i < n4; i += stride) {
        float4 v = __ldcs(X + i);
        g_xh[i] = make_uint2(h2_bits(__floats2half2_rn(v.x, v.y)),
                             h2_bits(__floats2half2_rn(v.z, v.w)));
    }

    const bool is64 = detect64(edges);
    if (is64) {
        const long long* s = (const long long*)edges;
        for (int e = tid; e < E; e += stride)
            atomicAdd(&g_count[(int)s[e]], 1);
    } else {
        const int* s = (const int*)edges;
        for (int e = tid; e < E; e += stride)
            atomicAdd(&g_count[s[e]], 1);
    }
}

__global__ void scan1_kernel() {
    __shared__ int sh[SCAN_BLK];
    int i = blockIdx.x * SCAN_BLK + threadIdx.x;
    int v = g_count[i];
    sh[threadIdx.x] = v;
    __syncthreads();
    #pragma unroll
    for (int off = 1; off < SCAN_BLK; off <<= 1) {
        int t = (threadIdx.x >= off) ? sh[threadIdx.x - off] : 0;
        __syncthreads();
        sh[threadIdx.x] += t;
        __syncthreads();
    }
    g_rowptr[i] = sh[threadIdx.x] - v;
    if (threadIdx.x == SCAN_BLK - 1) g_blocksums[blockIdx.x] = sh[threadIdx.x];
}

__global__ void scan2_kernel(int nblocks) {
    __shared__ int sh[128];
    int v = (threadIdx.x < nblocks) ? g_blocksums[threadIdx.x] : 0;
    sh[threadIdx.x] = v;
    __syncthreads();
    #pragma unroll
    for (int off = 1; off < 128; off <<= 1) {
        int t = (threadIdx.x >= off) ? sh[threadIdx.x - off] : 0;
        __syncthreads();
        sh[threadIdx.x] += t;
        __syncthreads();
    }
    if (threadIdx.x < nblocks) g_blocksums[threadIdx.x] = sh[threadIdx.x] - v;
}

__global__ void scan3_kernel(int npad) {
    int i = blockIdx.x * blockDim.x + threadIdx.x;
    if (i < npad) {
        int r = g_rowptr[i] + g_blocksums[i / SCAN_BLK];
        g_rowptr[i] = r;
        g_cursor[i] = r;
    }
}

// Scatter packed (dst<<8, att bits): byte-offset shift runs here (ALU idle).
__global__ void scatter_kernel(const void* __restrict__ edges,
                               const float* __restrict__ att, int E) {
    const bool is64 = detect64(edges);
    int half = E >> 1;
    int stride = gridDim.x * blockDim.x;
    for (int i = blockIdx.x * blockDim.x + threadIdx.x; i < half; i += stride) {
        int s0, s1, d0, d1;
        if (is64) {
            longlong2 s = __ldcs((const longlong2*)edges + i);
            longlong2 d = __ldcs((const longlong2*)((const long long*)edges + E) + i);
            s0 = (int)s.x; s1 = (int)s.y; d0 = (int)d.x; d1 = (int)d.y;
        } else {
            int2 s = __ldcs((const int2*)edges + i);
            int2 d = __ldcs((const int2*)((const int*)edges + E) + i);
            s0 = s.x; s1 = s.y; d0 = d.x; d1 = d.y;
        }
        float2 a = __ldcs((const float2*)att + i);
        int p0 = atomicAdd(&g_cursor[s0], 1);
        g_edge[p0] = make_int2(d0 << 8, __float_as_int(a.x));
        int p1 = atomicAdd(&g_cursor[s1], 1);
        g_edge[p1] = make_int2(d1 << 8, __float_as_int(a.y));
    }
    if (blockIdx.x == 0 && threadIdx.x == 0 && (E & 1)) {
        int e = E - 1;
        int s, d;
        if (is64) {
            s = (int)((const long long*)edges)[e];
            d = (int)((const long long*)edges)[(long long)E + e];
        } else {
            s = ((const int*)edges)[e];
            d = ((const int*)edges)[(long long)E + e];
        }
        int p = atomicAdd(&g_cursor[s], 1);
        g_edge[p] = make_int2(d << 8, __float_as_int(att[e]));
    }
}

// 8 fp16 -> 8 fp32 FMA into two float4 accumulators.
__device__ __forceinline__ void fma8(uint4 h, float a, float4& acc0, float4& acc1) {
    float2 f0 = __half22float2(*(__half2*)&h.x);
    float2 f1 = __half22float2(*(__half2*)&h.y);
    float2 f2 = __half22float2(*(__half2*)&h.z);
    float2 f3 = __half22float2(*(__half2*)&h.w);
    acc0.x = fmaf(a, f0.x, acc0.x); acc0.y = fmaf(a, f0.y, acc0.y);
    acc0.z = fmaf(a, f1.x, acc0.z); acc0.w = fmaf(a, f1.y, acc0.w);
    acc1.x = fmaf(a, f2.x, acc1.x); acc1.y = fmaf(a, f2.y, acc1.y);
    acc1.z = fmaf(a, f3.x, acc1.z); acc1.w = fmaf(a, f3.y, acc1.w);
}

// Warp per node, halves process even/odd edges of the same list.
// Lane = (hf, sub): gathers uint4 at row_byte_offset + sub*16.
// Epilogue: acc += shfl_xor(acc, 16); half0 stores even float4, half1 odd.
__global__ void __launch_bounds__(256) spmm_kernel(float4* __restrict__ out, int N) {
    int lane = threadIdx.x & 31;
    int hf = lane >> 4;                    // 0: even edges, 1: odd edges
    int sub = lane & 15;
    int node = (blockIdx.x * blockDim.x + threadIdx.x) >> 5;
    if (node >= N) return;

    int e = __ldg(&g_rowptr[node]);
    int end = __ldg(&g_rowptr[node + 1]);
    if (lane == 0) g_count[node] = 0;      // restore zero-invariant

    const char* xb = (const char*)g_xh + (sub << 4);   // lane's 16B within row
    float4 acc0 = make_float4(0.f, 0.f, 0.f, 0.f);
    float4 acc1 = make_float4(0.f, 0.f, 0.f, 0.f);

    // main: 4 pairs (8 edges) per iteration; my half handles e+2k+hf
    for (; e + 8 <= end; e += 8) {
        int2 m[4]; uint4 h[4];
        #pragma unroll
        for (int k = 0; k < 4; k++) m[k] = __ldg(&g_edge[e + 2 * k + hf]);
        #pragma unroll
        for (int k = 0; k < 4; k++)
            h[k] = __ldg((const uint4*)(xb + (unsigned)m[k].x));
        #pragma unroll
        for (int k = 0; k < 4; k++)
            fma8(h[k], __int_as_float(m[k].y), acc0, acc1);
    }
    // remaining pairs
    for (; e + 2 <= end; e += 2) {
        int2 m = __ldg(&g_edge[e + hf]);
        uint4 h = __ldg((const uint4*)(xb + (unsigned)m.x));
        fma8(h, __int_as_float(m.y), acc0, acc1);
    }
    // odd tail: both halves load it; upper half contributes 0
    if (e < end) {
        int2 m = __ldg(&g_edge[e]);
        uint4 h = __ldg((const uint4*)(xb + (unsigned)m.x));
        float a = hf ? 0.f : __int_as_float(m.y);
        fma8(h, a, acc0, acc1);
    }

    // combine halves (feats identical across halves)
    const unsigned FULL = 0xFFFFFFFFu;
    acc0.x += __shfl_xor_sync(FULL, acc0.x, 16);
    acc0.y += __shfl_xor_sync(FULL, acc0.y, 16);
    acc0.z += __shfl_xor_sync(FULL, acc0.z, 16);
    acc0.w += __shfl_xor_sync(FULL, acc0.w, 16);
    acc1.x += __shfl_xor_sync(FULL, acc1.x, 16);
    acc1.y += __shfl_xor_sync(FULL, acc1.y, 16);
    acc1.z += __shfl_xor_sync(FULL, acc1.z, 16);
    acc1.w += __shfl_xor_sync(FULL, acc1.w, 16);

    // lane (hf, sub) stores float4 index sub*2 + hf  -> 512B coalesced row
    __stcs(out + (size_t)node * 32 + sub * 2 + hf, hf ? acc1 : acc0);
}

extern "C" void kernel_launch(void* const* d_in, const int* in_sizes, int n_in,
                              void* d_out, int out_size) {
    const void* edges = d_in[0];               // (2, E) int32 or int64
    const float* att = (const float*)d_in[1];  // (E,)
    const float4* X = (const float4*)d_in[3];  // (N, 128) fp32
    float4* out = (float4*)d_out;

    int E = in_sizes[1];
    int N = out_size / 128;
    int npad = ((N + 1 + SCAN_BLK - 1) / SCAN_BLK) * SCAN_BLK;
    int nsb = npad / SCAN_BLK;

    prep_hist_kernel<<<2048, 256>>>(X, N, edges, E);
    scan1_kernel<<<nsb, SCAN_BLK>>>();
    scan2_kernel<<<1, 128>>>(nsb);
    scan3_kernel<<<(npad + 255) / 256, 256>>>(npad);
    scatter_kernel<<<2048, 256>>>(edges, att, E);
    spmm_kernel<<<(N + 7) / 8, 256>>>(out, N);
}